// round 3
// baseline (speedup 1.0000x reference)
#include <cuda_runtime.h>

// Problem constants
#define B_  2
#define N_  2048
#define D_  1024
#define H_  16
#define DH  64
#define M_  (B_ * N_)   // 4096 rows

// Scratch (device globals — no allocation allowed)
__device__ float g_Q[M_ * D_];
__device__ float g_K[M_ * D_];
__device__ float g_V[M_ * D_];
__device__ float g_C[M_ * D_];

// ---------------------------------------------------------------------------
// Packed f32x2 helpers (Blackwell FFMA2 — 2 FMAs per fma-pipe instruction)
// ---------------------------------------------------------------------------
typedef unsigned long long u64;

__device__ __forceinline__ u64 pack2(float x, float y) {
    u64 r; asm("mov.b64 %0, {%1,%2};" : "=l"(r) : "f"(x), "f"(y)); return r;
}
__device__ __forceinline__ float2 unpack2(u64 v) {
    float2 r; asm("mov.b64 {%0,%1}, %2;" : "=f"(r.x), "=f"(r.y) : "l"(v)); return r;
}
__device__ __forceinline__ u64 ffma2(u64 a, u64 b, u64 c) {
    u64 d; asm("fma.rn.f32x2 %0, %1, %2, %3;" : "=l"(d) : "l"(a), "l"(b), "l"(c)); return d;
}
__device__ __forceinline__ u64 fmul2(u64 a, u64 b) {
    u64 d; asm("mul.rn.f32x2 %0, %1, %2;" : "=l"(d) : "l"(a), "l"(b)); return d;
}

// ---------------------------------------------------------------------------
// NT SGEMM tile: C[m][n] = sum_k A[m][k] * W[n][k] (+ bias[n])
// A: [*, 1024] row-major, W: [1024, 1024] row-major (torch Linear weight),
// BM=BN=128, BK=8, 256 threads, 8x8 per thread, register prefetch.
// ---------------------------------------------------------------------------
__device__ __forceinline__ void gemm_tile(const float* __restrict__ A,
                                          const float* __restrict__ W,
                                          float* __restrict__ C,
                                          const float* __restrict__ bias)
{
    __shared__ float As[8][128];
    __shared__ float Ws[8][128];

    const int tid = threadIdx.x;          // 0..255
    const int tx  = tid & 15;             // 0..15 (N direction)
    const int ty  = tid >> 4;             // 0..15 (M direction)
    const int mbase = blockIdx.y * 128;
    const int nbase = blockIdx.x * 128;

    // Global-load mapping: each thread loads one float4 per tile per matrix.
    const int lr = tid >> 1;              // row within 128-row tile
    const int lc = (tid & 1) * 4;         // 0 or 4 within the 8-wide K slab
    const float* Ap = A + (size_t)(mbase + lr) * D_ + lc;
    const float* Wp = W + (size_t)(nbase + lr) * D_ + lc;

    float acc[8][8];
    #pragma unroll
    for (int i = 0; i < 8; i++)
        #pragma unroll
        for (int j = 0; j < 8; j++)
            acc[i][j] = 0.0f;

    float4 av = *(const float4*)(Ap);
    float4 wv = *(const float4*)(Wp);

    for (int kb = 0; kb < D_; kb += 8) {
        // store current slab (transposed: [k][row]) — 2-way STS conflict, acceptable
        As[lc + 0][lr] = av.x; As[lc + 1][lr] = av.y;
        As[lc + 2][lr] = av.z; As[lc + 3][lr] = av.w;
        Ws[lc + 0][lr] = wv.x; Ws[lc + 1][lr] = wv.y;
        Ws[lc + 2][lr] = wv.z; Ws[lc + 3][lr] = wv.w;
        __syncthreads();

        // prefetch next slab while computing
        if (kb + 8 < D_) {
            av = *(const float4*)(Ap + kb + 8);
            wv = *(const float4*)(Wp + kb + 8);
        }

        #pragma unroll
        for (int k = 0; k < 8; k++) {
            float a[8], w[8];
            *(float4*)&a[0] = *(const float4*)&As[k][ty * 8];
            *(float4*)&a[4] = *(const float4*)&As[k][ty * 8 + 4];
            *(float4*)&w[0] = *(const float4*)&Ws[k][tx * 8];
            *(float4*)&w[4] = *(const float4*)&Ws[k][tx * 8 + 4];
            #pragma unroll
            for (int i = 0; i < 8; i++)
                #pragma unroll
                for (int j = 0; j < 8; j++)
                    acc[i][j] += a[i] * w[j];
        }
        __syncthreads();
    }

    #pragma unroll
    for (int i = 0; i < 8; i++) {
        const size_t r = (size_t)(mbase + ty * 8 + i) * D_;
        #pragma unroll
        for (int j4 = 0; j4 < 2; j4++) {
            const int c = nbase + tx * 8 + j4 * 4;
            float4 v;
            v.x = acc[i][j4 * 4 + 0];
            v.y = acc[i][j4 * 4 + 1];
            v.z = acc[i][j4 * 4 + 2];
            v.w = acc[i][j4 * 4 + 3];
            if (bias) {
                v.x += bias[c + 0]; v.y += bias[c + 1];
                v.z += bias[c + 2]; v.w += bias[c + 3];
            }
            *(float4*)(C + r + c) = v;
        }
    }
}

// Fused QKV projection: blockIdx.z selects which weight/output (x tiles L2-shared).
__global__ void __launch_bounds__(256) qkv_kernel(const float* __restrict__ x,
                                                  const float* __restrict__ Wq,
                                                  const float* __restrict__ Wk,
                                                  const float* __restrict__ Wv)
{
    const float* W;
    float* O;
    if (blockIdx.z == 0)      { W = Wq; O = g_Q; }
    else if (blockIdx.z == 1) { W = Wk; O = g_K; }
    else                      { W = Wv; O = g_V; }
    gemm_tile(x, W, O, nullptr);
}

// Output projection: out = ctx @ Wo^T + bo
__global__ void __launch_bounds__(256) outproj_kernel(const float* __restrict__ Wo,
                                                      const float* __restrict__ bo,
                                                      float* __restrict__ out)
{
    gemm_tile(g_C, Wo, out, bo);
}

// ---------------------------------------------------------------------------
// Flash attention (fp32, FFMA2 inner loops).
// Grid: (N_/128, B_*H_). Block: 128 threads; each thread owns ONE query row:
//   q[64] and o[64] live in registers as 32 packed f32x2 each.
// KV tiles of 32 rows x 64 cols staged in SMEM; online softmax.
// ---------------------------------------------------------------------------
__global__ void __launch_bounds__(128) flash_kernel()
{
    __shared__ float Ks[32][64];
    __shared__ float Vs[32][64];

    const int bh = blockIdx.y;
    const int b  = bh >> 4;
    const int h  = bh & 15;
    const int n  = blockIdx.x * 128 + threadIdx.x;     // query row (always < 2048)
    const size_t row = (size_t)(b * N_ + n) * D_ + h * DH;

    // Load + pre-scale q into packed registers
    u64 q2[32];
    {
        const float sc = 0.125f;  // dh^-0.5 = 64^-0.5
        #pragma unroll
        for (int d4 = 0; d4 < 16; d4++) {
            float4 t = *(const float4*)(g_Q + row + d4 * 4);
            q2[2 * d4]     = pack2(t.x * sc, t.y * sc);
            q2[2 * d4 + 1] = pack2(t.z * sc, t.w * sc);
        }
    }

    u64 o2[32];
    #pragma unroll
    for (int i = 0; i < 32; i++) o2[i] = 0ull;   // bit pattern of (0.f, 0.f)
    float m = -1e30f;
    float l = 0.0f;

    const size_t kvbase = (size_t)b * N_ * D_ + h * DH;

    for (int j0 = 0; j0 < N_; j0 += 32) {
        __syncthreads();   // previous tile fully consumed
        // Stage K,V tile: 32 rows x 64 floats each = 512 float4 per matrix
        #pragma unroll
        for (int r = 0; r < 4; r++) {
            const int f  = threadIdx.x + 128 * r;   // float4 index 0..511
            const int jr = f >> 4;
            const int c4 = (f & 15) * 4;
            const size_t g = kvbase + (size_t)(j0 + jr) * D_ + c4;
            *(float4*)&Ks[jr][c4] = *(const float4*)(g_K + g);
            *(float4*)&Vs[jr][c4] = *(const float4*)(g_V + g);
        }
        __syncthreads();

        // S = q . K_j (packed FFMA2, 4 independent accumulator chains)
        float s[32];
        float tmax = -1e30f;
        #pragma unroll
        for (int j = 0; j < 32; j++) {
            const ulonglong2* kp = (const ulonglong2*)&Ks[j][0];  // 16 x LDS.128
            u64 a0 = 0ull, a1 = 0ull, a2 = 0ull, a3 = 0ull;
            #pragma unroll
            for (int e = 0; e < 16; e += 2) {
                ulonglong2 ka = kp[e];
                ulonglong2 kb = kp[e + 1];
                a0 = ffma2(q2[2 * e + 0], ka.x, a0);
                a1 = ffma2(q2[2 * e + 1], ka.y, a1);
                a2 = ffma2(q2[2 * e + 2], kb.x, a2);
                a3 = ffma2(q2[2 * e + 3], kb.y, a3);
            }
            float2 t0 = unpack2(a0), t1 = unpack2(a1);
            float2 t2 = unpack2(a2), t3 = unpack2(a3);
            s[j] = ((t0.x + t0.y) + (t1.x + t1.y)) + ((t2.x + t2.y) + (t3.x + t3.y));
            tmax = fmaxf(tmax, s[j]);
        }

        // Online softmax update
        const float mnew = fmaxf(m, tmax);
        const float corr = __expf(m - mnew);   // first iter: exp(-inf-ish) = 0
        m = mnew;
        float ps = 0.0f;
        #pragma unroll
        for (int j = 0; j < 32; j++) { s[j] = __expf(s[j] - mnew); ps += s[j]; }
        l = l * corr + ps;

        const u64 c2 = pack2(corr, corr);
        #pragma unroll
        for (int i = 0; i < 32; i++) o2[i] = fmul2(o2[i], c2);

        // O += P . V (packed FFMA2)
        #pragma unroll
        for (int j = 0; j < 32; j++) {
            const u64 p2 = pack2(s[j], s[j]);
            const ulonglong2* vp = (const ulonglong2*)&Vs[j][0];
            #pragma unroll
            for (int e = 0; e < 16; e++) {
                ulonglong2 vv = vp[e];
                o2[2 * e]     = ffma2(p2, vv.x, o2[2 * e]);
                o2[2 * e + 1] = ffma2(p2, vv.y, o2[2 * e + 1]);
            }
        }
    }

    // Normalize and write context (same [row, h*64 + d] layout as Q)
    const float inv = 1.0f / l;
    const u64 i2 = pack2(inv, inv);
    #pragma unroll
    for (int e = 0; e < 16; e++) {
        ulonglong2 w;
        w.x = fmul2(o2[2 * e],     i2);
        w.y = fmul2(o2[2 * e + 1], i2);
        *(ulonglong2*)(g_C + row + e * 4) = w;
    }
}

// ---------------------------------------------------------------------------
// Launch
// ---------------------------------------------------------------------------
extern "C" void kernel_launch(void* const* d_in, const int* in_sizes, int n_in,
                              void* d_out, int out_size)
{
    (void)in_sizes; (void)n_in; (void)out_size;
    const float* x  = (const float*)d_in[0];
    const float* Wq = (const float*)d_in[1];
    const float* Wk = (const float*)d_in[2];
    const float* Wv = (const float*)d_in[3];
    const float* Wo = (const float*)d_in[4];
    const float* bo = (const float*)d_in[5];
    float* out = (float*)d_out;

    dim3 gq(D_ / 128, M_ / 128, 3);      // 8 x 32 x 3
    qkv_kernel<<<gq, 256>>>(x, Wq, Wk, Wv);

    dim3 ga(N_ / 128, B_ * H_);          // 16 x 32
    flash_kernel<<<ga, 128>>>();

    dim3 go(D_ / 128, M_ / 128);         // 8 x 32
    outproj_kernel<<<go, 256>>>(Wo, bo, out);
}